// round 17
// baseline (speedup 1.0000x reference)
#include <cuda_runtime.h>
#include <cuda_fp16.h>
#include <cstddef>

#define K_DIM 4096
#define N_DIM 4096
#define M_DIM 8192
#define GROUP_SHIFT 7   // group_size = 128

// ---------------------------------------------------------------------------
// Device scratch
// ---------------------------------------------------------------------------
__device__ __half g_Wdeq[(size_t)K_DIM * N_DIM];         // dequant+gathered W'
__device__ __half g_bias[N_DIM];

// ---------------------------------------------------------------------------
// Kernel 1 (no predecessor):
//   blocks [0,512) : dequant one packed qw row -> 8 gathered W' rows
//                    (perm lookup in-block by scanning invperm)
//   block 512      : bias f32 -> f16
// Harness serves fp16 reference tensors as float32 (R1 1.33e34 fingerprint).
// x is consumed directly (f32) by the GEMM — no convert pass.
// ---------------------------------------------------------------------------
#define DEQ_BLOCKS (K_DIM / 8)          // 512

__global__ void prep_kernel(const int* __restrict__ qw,
                            const int* __restrict__ qs,
                            const float* __restrict__ smax_in,
                            const float* __restrict__ bias_in,
                            const int* __restrict__ invperm) {
    const int b = blockIdx.x;
    if (b == DEQ_BLOCKS) {
        for (int n = threadIdx.x; n < N_DIM; n += 256)
            g_bias[n] = __float2half(bias_in[n]);
        return;
    }

    // ---- dequant: packed row k8 -> 8 gathered output rows ----
    const int k8 = b;                       // 0..511
    const int g  = k8 >> 4;                 // group (16 packed rows/group)
    const int t  = threadIdx.x;             // 256 threads, 16 n's each
    const int n0 = t * 16;

    // in-block perm lookup: find the 8 j with invperm[j] in [8k8, 8k8+8)
    __shared__ int s_j[8];
    const int base_k = k8 * 8;
#pragma unroll
    for (int it = 0; it < 16; ++it) {
        const int j = it * 256 + t;
        const int k = invperm[j];
        if ((k & ~7) == base_k) s_j[k & 7] = j;
    }

    // scales for this thread's 16 columns (fp16 math = reference order)
    const __half sm = __float2half(smax_in[g] * (1.0f / 256.0f));
    const int* qs_row = qs + g * (N_DIM / 8);
    const int s_w0 = qs_row[(n0 >> 3) + 0];
    const int s_w1 = qs_row[(n0 >> 3) + 1];
    __half sc[16];
#pragma unroll
    for (int i = 0; i < 16; ++i) {
        const int sw = (i < 8) ? s_w0 : s_w1;
        const int s4 = (sw >> ((i & 7) * 4)) & 0xF;
        const __half s1 = __int2half_rn(s4 + 1);
        sc[i] = __hmul(__hmul(s1, s1), sm);
    }

    // read the 16 packed ints once
    const int4* qw_row = reinterpret_cast<const int4*>(qw + (size_t)k8 * N_DIM);
    int wv[16];
    *reinterpret_cast<int4*>(&wv[0])  = qw_row[t * 4 + 0];
    *reinterpret_cast<int4*>(&wv[4])  = qw_row[t * 4 + 1];
    *reinterpret_cast<int4*>(&wv[8])  = qw_row[t * 4 + 2];
    *reinterpret_cast<int4*>(&wv[12]) = qw_row[t * 4 + 3];

    __syncthreads();                        // s_j ready

#pragma unroll
    for (int kk = 0; kk < 8; ++kk) {
        const int j = s_j[kk];
        const int shift = kk * 4;
        __half out[16];
#pragma unroll
        for (int i = 0; i < 16; ++i) {
            const int w4 = (wv[i] >> shift) & 0xF;
            out[i] = __hmul(__int2half_rn(w4 - 8), sc[i]);
        }
        __half* dst = g_Wdeq + (size_t)j * N_DIM + n0;
        *reinterpret_cast<uint4*>(dst)     = *reinterpret_cast<uint4*>(&out[0]);
        *reinterpret_cast<uint4*>(dst + 8) = *reinterpret_cast<uint4*>(&out[8]);
    }
}

// ---------------------------------------------------------------------------
// Kernel 2: fp16 GEMM, C = x @ W' + bias, fp32 accumulate, m16n8k16 HMMA.
// Consumer body identical to the 652-us plateau config (BK=32, 5 stages,
// one sync/iter). Producer change ONLY: A read as f32 from x and converted
// in-register (LDG f32 -> cvt -> STS f16); B stays cp.async from g_Wdeq.
// ---------------------------------------------------------------------------
#define BM 128
#define BN 128
#define BK 32
#define STAGES 5
#define THREADS 256
#define A_STRIDE (BK + 8)               // 40 halfs
#define B_STRIDE (BN + 8)               // 136 halfs
#define A_STAGE_ELEMS (BM * A_STRIDE)   // 5120 halfs
#define B_STAGE_ELEMS (BK * B_STRIDE)   // 4352 halfs
#define SMEM_BYTES ((STAGES * (A_STAGE_ELEMS + B_STAGE_ELEMS)) * 2)  // 94720 B

__device__ __forceinline__ unsigned smem_u32(const void* p) {
    return (unsigned)__cvta_generic_to_shared(p);
}
__device__ __forceinline__ void cp_async16(unsigned s, const void* g) {
    asm volatile("cp.async.cg.shared.global [%0], [%1], 16;\n" :: "r"(s), "l"(g));
}
__device__ __forceinline__ void cp_commit() {
    asm volatile("cp.async.commit_group;\n");
}
template <int N>
__device__ __forceinline__ void cp_wait() {
    asm volatile("cp.async.wait_group %0;\n" :: "n"(N));
}
__device__ __forceinline__ void ldsm_x4(unsigned& r0, unsigned& r1, unsigned& r2,
                                        unsigned& r3, unsigned addr) {
    asm volatile("ldmatrix.sync.aligned.m8n8.x4.shared.b16 {%0,%1,%2,%3}, [%4];\n"
                 : "=r"(r0), "=r"(r1), "=r"(r2), "=r"(r3) : "r"(addr));
}
__device__ __forceinline__ void ldsm_x4_trans(unsigned& r0, unsigned& r1, unsigned& r2,
                                              unsigned& r3, unsigned addr) {
    asm volatile("ldmatrix.sync.aligned.m8n8.x4.trans.shared.b16 {%0,%1,%2,%3}, [%4];\n"
                 : "=r"(r0), "=r"(r1), "=r"(r2), "=r"(r3) : "r"(addr));
}
__device__ __forceinline__ void mma16816(float* c, const unsigned* a, const unsigned* b) {
    asm volatile(
        "mma.sync.aligned.m16n8k16.row.col.f32.f16.f16.f32 "
        "{%0,%1,%2,%3}, {%4,%5,%6,%7}, {%8,%9}, {%0,%1,%2,%3};\n"
        : "+f"(c[0]), "+f"(c[1]), "+f"(c[2]), "+f"(c[3])
        : "r"(a[0]), "r"(a[1]), "r"(a[2]), "r"(a[3]), "r"(b[0]), "r"(b[1]));
}

// A: load 8 f32 from x, convert, store 16B to smem. B: cp.async from g_Wdeq.
__device__ __forceinline__ void load_tile(const float* __restrict__ X,
                                          const __half* __restrict__ Bw,
                                          __half* sa, __half* sb,
                                          int bm, int bn, int kt, int tid) {
    const __half* Bg = Bw + (size_t)(kt * BK) * N_DIM + bn;
#pragma unroll
    for (int i = 0; i < 2; ++i) {
        const int c  = tid + i * THREADS;
        const int ar = c >> 2, ac = (c & 3) << 3;     // 128 rows x 4 chunks
        const float* src = X + (size_t)(bm + ar) * K_DIM + kt * BK + ac;
        const float4 f0 = reinterpret_cast<const float4*>(src)[0];
        const float4 f1 = reinterpret_cast<const float4*>(src)[1];
        __half2 h[4];
        h[0] = __floats2half2_rn(f0.x, f0.y);
        h[1] = __floats2half2_rn(f0.z, f0.w);
        h[2] = __floats2half2_rn(f1.x, f1.y);
        h[3] = __floats2half2_rn(f1.z, f1.w);
        *reinterpret_cast<uint4*>(sa + ar * A_STRIDE + ac) =
            *reinterpret_cast<uint4*>(h);

        const int br = c >> 4, bc = (c & 15) << 3;    // 32 rows x 16 chunks
        cp_async16(smem_u32(sb + br * B_STRIDE + bc), Bg + (size_t)br * N_DIM + bc);
    }
}

__global__ void __launch_bounds__(THREADS, 2)
gemm_kernel(const float* __restrict__ X, float* __restrict__ Cout) {
    extern __shared__ __half smem[];
    __half* sA = smem;
    __half* sB = smem + STAGES * A_STAGE_ELEMS;

    const int tid  = threadIdx.x;
    const int wid  = tid >> 5;
    const int lane = tid & 31;
    const int bm = blockIdx.y * BM;
    const int bn = blockIdx.x * BN;

    cudaGridDependencySynchronize();   // g_Wdeq / g_bias ready (x is input)

    const __half* Bw = g_Wdeq;

#pragma unroll
    for (int s = 0; s < STAGES - 1; ++s) {
        load_tile(X, Bw, sA + s * A_STAGE_ELEMS, sB + s * B_STAGE_ELEMS, bm, bn, s, tid);
        cp_commit();
    }

    float acc[2][8][4];
#pragma unroll
    for (int mi = 0; mi < 2; ++mi)
#pragma unroll
        for (int ni = 0; ni < 8; ++ni)
#pragma unroll
            for (int r = 0; r < 4; ++r) acc[mi][ni][r] = 0.0f;

    const int wm = (wid >> 1) * 32;   // warp m offset (4 warp rows)
    const int wn = (wid & 1) * 64;    // warp n offset (2 warp cols)

    const int KT = K_DIM / BK;        // 128
    int stage = 0;

    for (int kt = 0; kt < KT; ++kt) {
        cp_wait<STAGES - 2>();
        __syncthreads();

        const __half* sa = sA + stage * A_STAGE_ELEMS;
        const __half* sb = sB + stage * B_STAGE_ELEMS;

#pragma unroll
        for (int kk = 0; kk < 2; ++kk) {
            unsigned a[2][4];
#pragma unroll
            for (int mi = 0; mi < 2; ++mi) {
                const int row = wm + mi * 16 + (lane & 15);
                const int col = kk * 16 + ((lane >> 4) << 3);
                ldsm_x4(a[mi][0], a[mi][1], a[mi][2], a[mi][3],
                        smem_u32(sa + row * A_STRIDE + col));
            }
            unsigned b[4][4];
#pragma unroll
            for (int ni = 0; ni < 4; ++ni) {
                const int row = kk * 16 + (lane & 15);
                const int col = wn + ni * 16 + ((lane >> 4) << 3);
                ldsm_x4_trans(b[ni][0], b[ni][1], b[ni][2], b[ni][3],
                              smem_u32(sb + row * B_STRIDE + col));
            }
#pragma unroll
            for (int mi = 0; mi < 2; ++mi)
#pragma unroll
                for (int ni = 0; ni < 4; ++ni) {
                    mma16816(acc[mi][2 * ni + 0], a[mi], &b[ni][0]);
                    mma16816(acc[mi][2 * ni + 1], a[mi], &b[ni][2]);
                }
        }

        const int nt = kt + STAGES - 1;
        if (nt < KT) {
            int ns = stage + (STAGES - 1);
            if (ns >= STAGES) ns -= STAGES;
            load_tile(X, Bw, sA + ns * A_STAGE_ELEMS, sB + ns * B_STAGE_ELEMS,
                      bm, bn, nt, tid);
        }
        cp_commit();

        if (++stage == STAGES) stage = 0;
    }

    // Epilogue: fp32 acc -> fp16 (+ fp16 bias), store as f32 (output dtype)
#pragma unroll
    for (int mi = 0; mi < 2; ++mi) {
#pragma unroll
        for (int ni = 0; ni < 8; ++ni) {
            const int n  = bn + wn + ni * 8 + ((lane & 3) << 1);
            const __half2 bv = *reinterpret_cast<const __half2*>(g_bias + n);
            const int m0 = bm + wm + mi * 16 + (lane >> 2);
            float* c = acc[mi][ni];
            const __half2 r0 = __hadd2(__floats2half2_rn(c[0], c[1]), bv);
            const __half2 r1 = __hadd2(__floats2half2_rn(c[2], c[3]), bv);
            const size_t o0 = (size_t)m0 * N_DIM + n;
            const size_t o1 = (size_t)(m0 + 8) * N_DIM + n;
            float2 f0 = { __low2float(r0), __high2float(r0) };
            float2 f1 = { __low2float(r1), __high2float(r1) };
            reinterpret_cast<float2*>(Cout)[o0 >> 1] = f0;
            reinterpret_cast<float2*>(Cout)[o1 >> 1] = f1;
        }
    }
}

// ---------------------------------------------------------------------------
extern "C" void kernel_launch(void* const* d_in, const int* in_sizes, int n_in,
                              void* d_out, int out_size) {
    const float* x    = (const float*)d_in[0];
    const int*   qw   = (const int*)d_in[1];
    const int*   qs   = (const int*)d_in[2];
    const float* smax = (const float*)d_in[3];
    const int*   invp = (const int*)d_in[4];
    const float* bias = (const float*)d_in[5];

    prep_kernel<<<DEQ_BLOCKS + 1, 256>>>(qw, qs, smax, bias, invp);

    cudaFuncSetAttribute(gemm_kernel, cudaFuncAttributeMaxDynamicSharedMemorySize,
                         SMEM_BYTES);

    cudaLaunchAttribute pdl[1];
    pdl[0].id = cudaLaunchAttributeProgrammaticStreamSerialization;
    pdl[0].val.programmaticStreamSerializationAllowed = 1;
    cudaLaunchConfig_t cfg = {};
    cfg.gridDim  = dim3(N_DIM / BN, M_DIM / BM);   // (32, 64)
    cfg.blockDim = dim3(THREADS);
    cfg.dynamicSmemBytes = SMEM_BYTES;
    cfg.stream = 0;
    cfg.attrs = pdl;
    cfg.numAttrs = 1;
    cudaLaunchKernelEx(&cfg, gemm_kernel, x, (float*)d_out);
}